// round 10
// baseline (speedup 1.0000x reference)
#include <cuda_runtime.h>
#include <cuda_bf16.h>
#include <math.h>
#include <stdint.h>

#define NROWS 131072
#define QKV_STRIDE 25165824ll

__device__ float g_qkv[3ll * 25165824];
__device__ __nv_bfloat16 g_xbf[25165824];
__device__ __nv_bfloat16 g_att[25165824];
__device__ float g_x1[25165824];
__device__ __nv_bfloat16 g_x1bf[25165824];
__device__ __nv_bfloat16 g_h[100663296ll];
__device__ __nv_bfloat16 g_wbf[442368];   // qkv|proj|fc1|fc2 weights bf16 [k][n]

__device__ __forceinline__ int map_row(int r) {
    int wid = r >> 6, n = r & 63;
    int b = wid >> 6, w = wid & 63;
    int h  = ((w >> 3) << 3) + (n >> 3);
    int ww = ((w & 7) << 3) + (n & 7);
    int ho = (h + 4) & 63, wo = (ww + 4) & 63;
    return (b << 12) + (ho << 6) + wo;
}
__device__ __forceinline__ int region(int x) { return x < 56 ? 0 : (x < 60 ? 1 : 2); }

__device__ __forceinline__ void cpa16(unsigned s, const void* g) {
    asm volatile("cp.async.cg.shared.global [%0], [%1], 16;" :: "r"(s), "l"(g));
}
#define CP_COMMIT() asm volatile("cp.async.commit_group;")
#define CP_WAIT1()  asm volatile("cp.async.wait_group 1;")

__device__ __forceinline__ void ldsm4(unsigned* r, unsigned a) {
    asm volatile("ldmatrix.sync.aligned.m8n8.x4.shared.b16 {%0,%1,%2,%3}, [%4];"
        : "=r"(r[0]), "=r"(r[1]), "=r"(r[2]), "=r"(r[3]) : "r"(a));
}
__device__ __forceinline__ void ldsm4t(unsigned* r, unsigned a) {
    asm volatile("ldmatrix.sync.aligned.m8n8.x4.trans.shared.b16 {%0,%1,%2,%3}, [%4];"
        : "=r"(r[0]), "=r"(r[1]), "=r"(r[2]), "=r"(r[3]) : "r"(a));
}
__device__ __forceinline__ void mma_bf16(float* d, const unsigned* a, const unsigned* b) {
    asm volatile(
        "mma.sync.aligned.m16n8k16.row.col.f32.bf16.bf16.f32 "
        "{%0,%1,%2,%3}, {%4,%5,%6,%7}, {%8,%9}, {%0,%1,%2,%3};"
        : "+f"(d[0]), "+f"(d[1]), "+f"(d[2]), "+f"(d[3])
        : "r"(a[0]), "r"(a[1]), "r"(a[2]), "r"(a[3]), "r"(b[0]), "r"(b[1]));
}

template<int MODE, int NCOLS>
__device__ __forceinline__ void epi_store(
    int r, int c, float v, const float* __restrict__ bias,
    const float* __restrict__ aux, float* __restrict__ outf,
    __nv_bfloat16* __restrict__ outh)
{
    v += bias[c];
    if (MODE == 0) {
        int which = c / 192, rem = c % 192;
        int head = rem >> 5, hd = rem & 31;
        if (which == 0) v *= 0.17677669529663689f;
        int wid = r >> 6, n = r & 63;
        outf[(long)which * QKV_STRIDE + (((long)(wid * 6 + head) * 64 + n) * 32 + hd)] = v;
    } else if (MODE == 1) {
        long o = (long)map_row(r) * 192 + c;
        float s = aux[o] + v;
        outf[o] = s;
        outh[o] = __float2bfloat16(s);
    } else if (MODE == 2) {
        outh[(long)r * NCOLS + c] =
            __float2bfloat16(0.5f * v * (1.0f + erff(v * 0.7071067811865476f)));
    } else {
        long o = (long)r * NCOLS + c;
        outf[o] = aux[o] + v;
    }
}

// ---------------------------------------------------------------------------
// bf16 mma.sync GEMM: block 256x64, BK=32, 3-stage cp.async pipeline,
// 8 warps (4M x 2N), warp tile 64x32 = 4x4 m16n8k16 frags (16 mma / 6 LDSM).
// A smem rows 80B pad; B smem rows 144B pad (conflict-free LDSM phases).
// ---------------------------------------------------------------------------
#define A_STAGE 20480   // 256 rows * 80B
#define B_STAGE 4608    // 32 rows * 144B
#define SMEM_TOTAL (3 * A_STAGE + 3 * B_STAGE + 16)

template<int MODE, int K, int NCOLS>
__global__ __launch_bounds__(256, 2) void gemm_bf16(
    const __nv_bfloat16* __restrict__ A, const __nv_bfloat16* __restrict__ Bm,
    const float* __restrict__ bias, const float* __restrict__ aux,
    float* __restrict__ outf, __nv_bfloat16* __restrict__ outh)
{
    extern __shared__ char smem_raw[];
    const unsigned aBase = (unsigned)__cvta_generic_to_shared(smem_raw);
    const unsigned bBase = aBase + 3 * A_STAGE;

    const int mBase = blockIdx.y * 256;
    const int nBase = blockIdx.x * 64;
    const int t = threadIdx.x;
    const int lane = t & 31, warp = t >> 5;
    const int warpM = warp >> 1, warpN = warp & 1;
    const int lq = lane >> 2, lr = lane & 3;

    // A loader: 4 rows per thread (ar + 64i), 16B chunk (t&3)
    const int ar = t >> 2;
    const int ac = (t & 3) * 8;
    const __nv_bfloat16* Ap[4];
    unsigned sA[4];
    #pragma unroll
    for (int i = 0; i < 4; i++) {
        int m = ar + 64 * i;
        long row = (MODE == 0) ? (long)map_row(mBase + m) : (long)(mBase + m);
        Ap[i] = A + row * K + ac;
        sA[i] = aBase + m * 80 + (t & 3) * 16;
    }
    // B loader: k = t>>3, 16B chunk (t&7)
    const int bk = t >> 3;
    const __nv_bfloat16* Bp = Bm + (long)bk * NCOLS + nBase + (t & 7) * 8;
    const unsigned sB = bBase + bk * 144 + (t & 7) * 16;

    float acc[4][4][4];
    #pragma unroll
    for (int mi = 0; mi < 4; mi++)
        #pragma unroll
        for (int ni = 0; ni < 4; ni++)
            #pragma unroll
            for (int e = 0; e < 4; e++) acc[mi][ni][e] = 0.f;

    const int NK = K / 32;
    #pragma unroll
    for (int s = 0; s < 2; s++) {
        #pragma unroll
        for (int i = 0; i < 4; i++) cpa16(sA[i] + s * A_STAGE, Ap[i] + s * 32);
        cpa16(sB + s * B_STAGE, Bp + (long)s * 32 * NCOLS);
        CP_COMMIT();
    }

    for (int kt = 0; kt < NK; kt++) {
        const int s = kt % 3;
        CP_WAIT1();
        __syncthreads();
        if (kt + 2 < NK) {
            const int s2 = (kt + 2) % 3;
            #pragma unroll
            for (int i = 0; i < 4; i++) cpa16(sA[i] + s2 * A_STAGE, Ap[i] + (kt + 2) * 32);
            cpa16(sB + s2 * B_STAGE, Bp + (long)(kt + 2) * 32 * NCOLS);
        }
        CP_COMMIT();

        const unsigned as0 = aBase + s * A_STAGE;
        const unsigned bs0 = bBase + s * B_STAGE;
        #pragma unroll
        for (int k16 = 0; k16 < 2; k16++) {
            unsigned af[4][4], bq[2][4];
            #pragma unroll
            for (int mi = 0; mi < 4; mi++)
                ldsm4(af[mi], as0 + (warpM * 64 + mi * 16 + (lane & 15)) * 80
                              + k16 * 32 + (lane >> 4) * 16);
            #pragma unroll
            for (int g = 0; g < 2; g++)
                ldsm4t(bq[g], bs0 + (k16 * 16 + (lane & 15)) * 144
                              + (warpN * 32 + g * 16 + ((lane >> 4) << 3)) * 2);
            #pragma unroll
            for (int mi = 0; mi < 4; mi++)
                #pragma unroll
                for (int ni = 0; ni < 4; ni++)
                    mma_bf16(acc[mi][ni], af[mi], &bq[ni >> 1][(ni & 1) * 2]);
        }
    }

    #pragma unroll
    for (int mi = 0; mi < 4; mi++) {
        int r0 = mBase + warpM * 64 + mi * 16 + lq;
        #pragma unroll
        for (int ni = 0; ni < 4; ni++) {
            int c0 = nBase + warpN * 32 + ni * 8 + lr * 2;
            epi_store<MODE, NCOLS>(r0,     c0,     acc[mi][ni][0], bias, aux, outf, outh);
            epi_store<MODE, NCOLS>(r0,     c0 + 1, acc[mi][ni][1], bias, aux, outf, outh);
            epi_store<MODE, NCOLS>(r0 + 8, c0,     acc[mi][ni][2], bias, aux, outf, outh);
            epi_store<MODE, NCOLS>(r0 + 8, c0 + 1, acc[mi][ni][3], bias, aux, outf, outh);
        }
    }
}

// ---------------------------------------------------------------------------
__global__ void f2bf(const float* __restrict__ in, __nv_bfloat16* __restrict__ out, int n) {
    int i = (blockIdx.x * blockDim.x + threadIdx.x) * 4;
    if (i >= n) return;
    float4 v = *(const float4*)(in + i);
    *(__nv_bfloat162*)(out + i)     = __floats2bfloat162_rn(v.x, v.y);
    *(__nv_bfloat162*)(out + i + 2) = __floats2bfloat162_rn(v.z, v.w);
}

// ---------------------------------------------------------------------------
// Attention: one block per (window, head). fp32 in, bf16 out.
// ---------------------------------------------------------------------------
__global__ __launch_bounds__(128) void attn_kernel(
    const float* __restrict__ rpb, __nv_bfloat16* __restrict__ out)
{
    __shared__ float Qs[64][32];
    __shared__ float Ks[64][32];
    __shared__ float Vs[64][32];
    __shared__ float S[64][65];

    const int bh = blockIdx.x;
    const int wid = bh / 6, head = bh - wid * 6;
    const int w = wid & 63;
    const int t = threadIdx.x;

    const float* qb = g_qkv + (long)bh * 2048;
    const float* kb = qb + QKV_STRIDE;
    const float* vb = kb + QKV_STRIDE;

    #pragma unroll
    for (int i = t; i < 512; i += 128) {
        ((float4*)Qs)[i] = ((const float4*)qb)[i];
        ((float4*)Ks)[i] = ((const float4*)kb)[i];
        ((float4*)Vs)[i] = ((const float4*)vb)[i];
    }
    __syncthreads();

    const int row = t >> 1, half = t & 1;
    const int cb = half << 5;

    float q[32];
    #pragma unroll
    for (int i = 0; i < 8; i++) {
        float4 v = *(const float4*)&Qs[row][i * 4];
        q[i * 4] = v.x; q[i * 4 + 1] = v.y; q[i * 4 + 2] = v.z; q[i * 4 + 3] = v.w;
    }

    const int hb  = (w >> 3) << 3;
    const int wbx = (w & 7) << 3;
    const int rh = row >> 3, rw = row & 7;
    const int regRow = region(hb + rh) * 3 + region(wbx + rw);

    float mx = -1e30f;
    for (int c = 0; c < 32; c++) {
        int col = cb + c;
        float acc = 0.f;
        const float* kpt = &Ks[col][0];
        #pragma unroll
        for (int i = 0; i < 8; i++) {
            float4 kv = *(const float4*)(kpt + i * 4);
            acc += q[i * 4] * kv.x + q[i * 4 + 1] * kv.y +
                   q[i * 4 + 2] * kv.z + q[i * 4 + 3] * kv.w;
        }
        int ch = col >> 3, cw = col & 7;
        acc += rpb[((rh - ch + 7) * 15 + (rw - cw + 7)) * 6 + head];
        int regC = region(hb + ch) * 3 + region(wbx + cw);
        if (regC != regRow) acc -= 100.f;
        S[row][col] = acc;
        mx = fmaxf(mx, acc);
    }
    mx = fmaxf(mx, __shfl_xor_sync(0xffffffffu, mx, 1));

    float lsum = 0.f;
    for (int c = 0; c < 32; c++) {
        float e = __expf(S[row][cb + c] - mx);
        S[row][cb + c] = e;
        lsum += e;
    }
    lsum += __shfl_xor_sync(0xffffffffu, lsum, 1);
    float inv = 1.f / lsum;
    __syncthreads();

    float o[16] = {};
    const int hd0 = half << 4;
    for (int m = 0; m < 64; m++) {
        float p = S[row][m];
        const float* vp = &Vs[m][hd0];
        #pragma unroll
        for (int i = 0; i < 4; i++) {
            float4 vv = *(const float4*)(vp + i * 4);
            o[i * 4]     += p * vv.x;
            o[i * 4 + 1] += p * vv.y;
            o[i * 4 + 2] += p * vv.z;
            o[i * 4 + 3] += p * vv.w;
        }
    }
    __nv_bfloat16* op = out + ((long)(wid * 64 + row)) * 192 + head * 32 + hd0;
    #pragma unroll
    for (int i = 0; i < 8; i++)
        ((__nv_bfloat162*)op)[i] = __floats2bfloat162_rn(o[2 * i] * inv, o[2 * i + 1] * inv);
}

// ---------------------------------------------------------------------------
extern "C" void kernel_launch(void* const* d_in, const int* in_sizes, int n_in,
                              void* d_out, int out_size)
{
    const float* x      = (const float*)d_in[0];
    const float* rpb    = (const float*)d_in[1];
    const float* qkv_w  = (const float*)d_in[2];
    const float* qkv_b  = (const float*)d_in[3];
    const float* proj_w = (const float*)d_in[4];
    const float* proj_b = (const float*)d_in[5];
    const float* fc1_w  = (const float*)d_in[6];
    const float* fc1_b  = (const float*)d_in[7];
    const float* fc2_w  = (const float*)d_in[8];
    const float* fc2_b  = (const float*)d_in[9];
    float* out = (float*)d_out;

    float *qkv, *x1;
    __nv_bfloat16 *xbf, *att, *x1bf, *h, *wbf;
    cudaGetSymbolAddress((void**)&qkv,  g_qkv);
    cudaGetSymbolAddress((void**)&xbf,  g_xbf);
    cudaGetSymbolAddress((void**)&att,  g_att);
    cudaGetSymbolAddress((void**)&x1,   g_x1);
    cudaGetSymbolAddress((void**)&x1bf, g_x1bf);
    cudaGetSymbolAddress((void**)&h,    g_h);
    cudaGetSymbolAddress((void**)&wbf,  g_wbf);

    cudaFuncSetAttribute(gemm_bf16<0, 192, 576>, cudaFuncAttributeMaxDynamicSharedMemorySize, SMEM_TOTAL);
    cudaFuncSetAttribute(gemm_bf16<1, 192, 192>, cudaFuncAttributeMaxDynamicSharedMemorySize, SMEM_TOTAL);
    cudaFuncSetAttribute(gemm_bf16<2, 192, 768>, cudaFuncAttributeMaxDynamicSharedMemorySize, SMEM_TOTAL);
    cudaFuncSetAttribute(gemm_bf16<3, 768, 192>, cudaFuncAttributeMaxDynamicSharedMemorySize, SMEM_TOTAL);

    f2bf<<<25165824 / 4 / 256, 256>>>(x, xbf, 25165824);
    f2bf<<<(110592 / 4 + 255) / 256, 256>>>(qkv_w,  wbf,          110592);
    f2bf<<<(36864  / 4 + 255) / 256, 256>>>(proj_w, wbf + 110592, 36864);
    f2bf<<<(147456 / 4 + 255) / 256, 256>>>(fc1_w,  wbf + 147456, 147456);
    f2bf<<<(147456 / 4 + 255) / 256, 256>>>(fc2_w,  wbf + 294912, 147456);

    gemm_bf16<0, 192, 576><<<dim3(9, 512),  256, SMEM_TOTAL>>>(xbf, wbf, qkv_b, nullptr, qkv, nullptr);
    attn_kernel<<<12288, 128>>>(rpb, att);
    gemm_bf16<1, 192, 192><<<dim3(3, 512),  256, SMEM_TOTAL>>>(att, wbf + 110592, proj_b, x, x1, x1bf);
    gemm_bf16<2, 192, 768><<<dim3(12, 512), 256, SMEM_TOTAL>>>(x1bf, wbf + 147456, fc1_b, nullptr, nullptr, h);
    gemm_bf16<3, 768, 192><<<dim3(3, 512),  256, SMEM_TOTAL>>>(h, wbf + 294912, fc2_b, x1, out, nullptr);
}

// round 11
// speedup vs baseline: 1.6338x; 1.6338x over previous
#include <cuda_runtime.h>
#include <cuda_bf16.h>
#include <math.h>
#include <stdint.h>

#define NROWS 131072
#define QKV_STRIDE 25165824ll

__device__ __nv_bfloat16 g_qkvh[3ll * 25165824];  // q,k,v bf16
__device__ __nv_bfloat16 g_xbf[25165824];
__device__ __nv_bfloat16 g_att[25165824];
__device__ float g_x1[25165824];
__device__ __nv_bfloat16 g_x1bf[25165824];
__device__ __nv_bfloat16 g_h[100663296ll];
__device__ __nv_bfloat16 g_wbf[442368];

__device__ __forceinline__ int map_row(int r) {
    int wid = r >> 6, n = r & 63;
    int b = wid >> 6, w = wid & 63;
    int h  = ((w >> 3) << 3) + (n >> 3);
    int ww = ((w & 7) << 3) + (n & 7);
    int ho = (h + 4) & 63, wo = (ww + 4) & 63;
    return (b << 12) + (ho << 6) + wo;
}
__device__ __forceinline__ int region(int x) { return x < 56 ? 0 : (x < 60 ? 1 : 2); }

__device__ __forceinline__ void cpa16(unsigned s, const void* g) {
    asm volatile("cp.async.cg.shared.global [%0], [%1], 16;" :: "r"(s), "l"(g));
}
#define CP_COMMIT() asm volatile("cp.async.commit_group;")
#define CP_WAIT1()  asm volatile("cp.async.wait_group 1;")

__device__ __forceinline__ void ldsm4(unsigned* r, unsigned a) {
    asm volatile("ldmatrix.sync.aligned.m8n8.x4.shared.b16 {%0,%1,%2,%3}, [%4];"
        : "=r"(r[0]), "=r"(r[1]), "=r"(r[2]), "=r"(r[3]) : "r"(a));
}
__device__ __forceinline__ void ldsm4t(unsigned* r, unsigned a) {
    asm volatile("ldmatrix.sync.aligned.m8n8.x4.trans.shared.b16 {%0,%1,%2,%3}, [%4];"
        : "=r"(r[0]), "=r"(r[1]), "=r"(r[2]), "=r"(r[3]) : "r"(a));
}
__device__ __forceinline__ void mma_bf16(float* d, const unsigned* a, const unsigned* b) {
    asm volatile(
        "mma.sync.aligned.m16n8k16.row.col.f32.bf16.bf16.f32 "
        "{%0,%1,%2,%3}, {%4,%5,%6,%7}, {%8,%9}, {%0,%1,%2,%3};"
        : "+f"(d[0]), "+f"(d[1]), "+f"(d[2]), "+f"(d[3])
        : "r"(a[0]), "r"(a[1]), "r"(a[2]), "r"(a[3]), "r"(b[0]), "r"(b[1]));
}

template<int MODE, int NCOLS>
__device__ __forceinline__ void epi_store(
    int r, int c, float v, const float* __restrict__ bias,
    const float* __restrict__ aux, float* __restrict__ outf,
    __nv_bfloat16* __restrict__ outh)
{
    v += bias[c];
    if (MODE == 0) {
        int which = c / 192, rem = c % 192;
        int head = rem >> 5, hd = rem & 31;
        if (which == 0) v *= 0.17677669529663689f;
        int wid = r >> 6, n = r & 63;
        outh[(long)which * QKV_STRIDE + (((long)(wid * 6 + head) * 64 + n) * 32 + hd)] =
            __float2bfloat16(v);
    } else if (MODE == 1) {
        long o = (long)map_row(r) * 192 + c;
        float s = aux[o] + v;
        outf[o] = s;
        outh[o] = __float2bfloat16(s);
    } else if (MODE == 2) {
        outh[(long)r * NCOLS + c] =
            __float2bfloat16(0.5f * v * (1.0f + erff(v * 0.7071067811865476f)));
    } else {
        long o = (long)r * NCOLS + c;
        outf[o] = aux[o] + v;
    }
}

// ---------------------------------------------------------------------------
// bf16 mma.sync GEMM: block 128 x NTILE, BK=32, 3-stage cp.async pipeline,
// 8 warps (4M x 2N), warp tile 32 x NTILE/2. A rows 80B pad, B rows 2*NTILE+16.
// ---------------------------------------------------------------------------
#define A_STAGE 10240   // 128 rows * 80B

template<int MODE, int K, int NCOLS, int NTILE>
__global__ __launch_bounds__(256) void gemm_bf16(
    const __nv_bfloat16* __restrict__ A, const __nv_bfloat16* __restrict__ Bm,
    const float* __restrict__ bias, const float* __restrict__ aux,
    float* __restrict__ outf, __nv_bfloat16* __restrict__ outh)
{
    constexpr int BROW = 2 * NTILE + 16;        // B smem row bytes
    constexpr int B_STAGE = 32 * BROW;
    constexpr int G  = NTILE / 32;              // ldsm4t groups per warp
    constexpr int NI = NTILE / 16;              // 8-col frag count per warp
    constexpr int CPT = NTILE / 64;             // B chunks per thread

    extern __shared__ char smem_raw[];
    const unsigned aBase = (unsigned)__cvta_generic_to_shared(smem_raw);
    const unsigned bBase = aBase + 3 * A_STAGE;

    const int mBase = blockIdx.y * 128;
    const int nBase = blockIdx.x * NTILE;
    const int t = threadIdx.x;
    const int lane = t & 31, warp = t >> 5;
    const int warpM = warp >> 1, warpN = warp & 1;
    const int lq = lane >> 2, lr = lane & 3;

    // A loader: rows ar, ar+64; 16B chunk (t&3)
    const int ar = t >> 2;
    const int ac = (t & 3) * 8;
    long row1 = (MODE == 0) ? (long)map_row(mBase + ar)      : (long)(mBase + ar);
    long row2 = (MODE == 0) ? (long)map_row(mBase + ar + 64) : (long)(mBase + ar + 64);
    const __nv_bfloat16* Ap1 = A + row1 * K + ac;
    const __nv_bfloat16* Ap2 = A + row2 * K + ac;
    const unsigned sA1 = aBase + ar * 80 + (t & 3) * 16;
    const unsigned sA2 = sA1 + 64 * 80;
    // B loader: k row t>>3, chunk(s) t&7 (+8)
    const int bk = t >> 3;
    const __nv_bfloat16* Bp = Bm + (long)bk * NCOLS + nBase + (t & 7) * 8;
    const unsigned sB = bBase + bk * BROW + (t & 7) * 16;

    float acc[2][NI][4];
    #pragma unroll
    for (int mi = 0; mi < 2; mi++)
        #pragma unroll
        for (int ni = 0; ni < NI; ni++)
            #pragma unroll
            for (int e = 0; e < 4; e++) acc[mi][ni][e] = 0.f;

    const int NK = K / 32;
    #pragma unroll
    for (int s = 0; s < 2; s++) {
        cpa16(sA1 + s * A_STAGE, Ap1 + s * 32);
        cpa16(sA2 + s * A_STAGE, Ap2 + s * 32);
        #pragma unroll
        for (int cc = 0; cc < CPT; cc++)
            cpa16(sB + s * B_STAGE + cc * 128, Bp + (long)s * 32 * NCOLS + cc * 64);
        CP_COMMIT();
    }

    for (int kt = 0; kt < NK; kt++) {
        const int s = kt % 3;
        CP_WAIT1();
        __syncthreads();
        if (kt + 2 < NK) {
            const int s2 = (kt + 2) % 3;
            cpa16(sA1 + s2 * A_STAGE, Ap1 + (kt + 2) * 32);
            cpa16(sA2 + s2 * A_STAGE, Ap2 + (kt + 2) * 32);
            #pragma unroll
            for (int cc = 0; cc < CPT; cc++)
                cpa16(sB + s2 * B_STAGE + cc * 128,
                      Bp + (long)(kt + 2) * 32 * NCOLS + cc * 64);
        }
        CP_COMMIT();

        const unsigned as0 = aBase + s * A_STAGE;
        const unsigned bs0 = bBase + s * B_STAGE;
        #pragma unroll
        for (int k16 = 0; k16 < 2; k16++) {
            unsigned af[2][4], bq[G][4];
            #pragma unroll
            for (int mi = 0; mi < 2; mi++)
                ldsm4(af[mi], as0 + (warpM * 32 + mi * 16 + (lane & 15)) * 80
                              + k16 * 32 + (lane >> 4) * 16);
            #pragma unroll
            for (int g = 0; g < G; g++)
                ldsm4t(bq[g], bs0 + (k16 * 16 + (lane & 15)) * BROW
                              + (warpN * (NTILE / 2) + g * 16 + ((lane >> 4) << 3)) * 2);
            #pragma unroll
            for (int mi = 0; mi < 2; mi++)
                #pragma unroll
                for (int ni = 0; ni < NI; ni++)
                    mma_bf16(acc[mi][ni], af[mi], &bq[ni >> 1][(ni & 1) * 2]);
        }
    }

    #pragma unroll
    for (int mi = 0; mi < 2; mi++) {
        int r0 = mBase + warpM * 32 + mi * 16 + lq;
        #pragma unroll
        for (int ni = 0; ni < NI; ni++) {
            int c0 = nBase + warpN * (NTILE / 2) + ni * 8 + lr * 2;
            epi_store<MODE, NCOLS>(r0,     c0,     acc[mi][ni][0], bias, aux, outf, outh);
            epi_store<MODE, NCOLS>(r0,     c0 + 1, acc[mi][ni][1], bias, aux, outf, outh);
            epi_store<MODE, NCOLS>(r0 + 8, c0,     acc[mi][ni][2], bias, aux, outf, outh);
            epi_store<MODE, NCOLS>(r0 + 8, c0 + 1, acc[mi][ni][3], bias, aux, outf, outh);
        }
    }
}

// ---------------------------------------------------------------------------
__global__ void f2bf(const float* __restrict__ in, __nv_bfloat16* __restrict__ out, int n) {
    int i = (blockIdx.x * blockDim.x + threadIdx.x) * 4;
    if (i >= n) return;
    float4 v = *(const float4*)(in + i);
    *(__nv_bfloat162*)(out + i)     = __floats2bfloat162_rn(v.x, v.y);
    *(__nv_bfloat162*)(out + i + 2) = __floats2bfloat162_rn(v.z, v.w);
}

// ---------------------------------------------------------------------------
// Attention: one block per (window, head). bf16 qkv in, fp32 smem, bf16 out.
// ---------------------------------------------------------------------------
__global__ __launch_bounds__(128) void attn_kernel(
    const float* __restrict__ rpb, __nv_bfloat16* __restrict__ out)
{
    __shared__ float Qs[64][32];
    __shared__ float Ks[64][32];
    __shared__ float Vs[64][32];
    __shared__ float S[64][65];

    const int bh = blockIdx.x;
    const int wid = bh / 6, head = bh - wid * 6;
    const int w = wid & 63;
    const int t = threadIdx.x;

    const __nv_bfloat16* qb = g_qkvh + (long)bh * 2048;
    const __nv_bfloat16* kb = qb + QKV_STRIDE;
    const __nv_bfloat16* vb = kb + QKV_STRIDE;

    #pragma unroll
    for (int i = t; i < 1024; i += 128) {
        ((float2*)Qs)[i] = __bfloat1622float2(((const __nv_bfloat162*)qb)[i]);
        ((float2*)Ks)[i] = __bfloat1622float2(((const __nv_bfloat162*)kb)[i]);
        ((float2*)Vs)[i] = __bfloat1622float2(((const __nv_bfloat162*)vb)[i]);
    }
    __syncthreads();

    const int row = t >> 1, half = t & 1;
    const int cb = half << 5;

    float q[32];
    #pragma unroll
    for (int i = 0; i < 8; i++) {
        float4 v = *(const float4*)&Qs[row][i * 4];
        q[i * 4] = v.x; q[i * 4 + 1] = v.y; q[i * 4 + 2] = v.z; q[i * 4 + 3] = v.w;
    }

    const int hb  = (w >> 3) << 3;
    const int wbx = (w & 7) << 3;
    const int rh = row >> 3, rw = row & 7;
    const int regRow = region(hb + rh) * 3 + region(wbx + rw);

    float mx = -1e30f;
    for (int c = 0; c < 32; c++) {
        int col = cb + c;
        float acc = 0.f;
        const float* kpt = &Ks[col][0];
        #pragma unroll
        for (int i = 0; i < 8; i++) {
            float4 kv = *(const float4*)(kpt + i * 4);
            acc += q[i * 4] * kv.x + q[i * 4 + 1] * kv.y +
                   q[i * 4 + 2] * kv.z + q[i * 4 + 3] * kv.w;
        }
        int ch = col >> 3, cw = col & 7;
        acc += rpb[((rh - ch + 7) * 15 + (rw - cw + 7)) * 6 + head];
        int regC = region(hb + ch) * 3 + region(wbx + cw);
        if (regC != regRow) acc -= 100.f;
        S[row][col] = acc;
        mx = fmaxf(mx, acc);
    }
    mx = fmaxf(mx, __shfl_xor_sync(0xffffffffu, mx, 1));

    float lsum = 0.f;
    for (int c = 0; c < 32; c++) {
        float e = __expf(S[row][cb + c] - mx);
        S[row][cb + c] = e;
        lsum += e;
    }
    lsum += __shfl_xor_sync(0xffffffffu, lsum, 1);
    float inv = 1.f / lsum;
    __syncthreads();

    float o[16] = {};
    const int hd0 = half << 4;
    for (int m = 0; m < 64; m++) {
        float p = S[row][m];
        const float* vp = &Vs[m][hd0];
        #pragma unroll
        for (int i = 0; i < 4; i++) {
            float4 vv = *(const float4*)(vp + i * 4);
            o[i * 4]     += p * vv.x;
            o[i * 4 + 1] += p * vv.y;
            o[i * 4 + 2] += p * vv.z;
            o[i * 4 + 3] += p * vv.w;
        }
    }
    __nv_bfloat16* op = out + ((long)(wid * 64 + row)) * 192 + head * 32 + hd0;
    #pragma unroll
    for (int i = 0; i < 8; i++)
        ((__nv_bfloat162*)op)[i] = __floats2bfloat162_rn(o[2 * i] * inv, o[2 * i + 1] * inv);
}

// ---------------------------------------------------------------------------
extern "C" void kernel_launch(void* const* d_in, const int* in_sizes, int n_in,
                              void* d_out, int out_size)
{
    const float* x      = (const float*)d_in[0];
    const float* rpb    = (const float*)d_in[1];
    const float* qkv_w  = (const float*)d_in[2];
    const float* qkv_b  = (const float*)d_in[3];
    const float* proj_w = (const float*)d_in[4];
    const float* proj_b = (const float*)d_in[5];
    const float* fc1_w  = (const float*)d_in[6];
    const float* fc1_b  = (const float*)d_in[7];
    const float* fc2_w  = (const float*)d_in[8];
    const float* fc2_b  = (const float*)d_in[9];
    float* out = (float*)d_out;

    float *x1;
    __nv_bfloat16 *qkvh, *xbf, *att, *x1bf, *h, *wbf;
    cudaGetSymbolAddress((void**)&qkvh, g_qkvh);
    cudaGetSymbolAddress((void**)&xbf,  g_xbf);
    cudaGetSymbolAddress((void**)&att,  g_att);
    cudaGetSymbolAddress((void**)&x1,   g_x1);
    cudaGetSymbolAddress((void**)&x1bf, g_x1bf);
    cudaGetSymbolAddress((void**)&h,    g_h);
    cudaGetSymbolAddress((void**)&wbf,  g_wbf);

    constexpr int SM64  = 3 * (A_STAGE + 32 * 144);   // 44544
    constexpr int SM128 = 3 * (A_STAGE + 32 * 272);   // 56832
    cudaFuncSetAttribute(gemm_bf16<0, 192, 576, 64>,  cudaFuncAttributeMaxDynamicSharedMemorySize, SM64);
    cudaFuncSetAttribute(gemm_bf16<1, 192, 192, 64>,  cudaFuncAttributeMaxDynamicSharedMemorySize, SM64);
    cudaFuncSetAttribute(gemm_bf16<2, 192, 768, 128>, cudaFuncAttributeMaxDynamicSharedMemorySize, SM128);
    cudaFuncSetAttribute(gemm_bf16<3, 768, 192, 64>,  cudaFuncAttributeMaxDynamicSharedMemorySize, SM64);

    f2bf<<<25165824 / 4 / 256, 256>>>(x, xbf, 25165824);
    f2bf<<<(110592 / 4 + 255) / 256, 256>>>(qkv_w,  wbf,          110592);
    f2bf<<<(36864  / 4 + 255) / 256, 256>>>(proj_w, wbf + 110592, 36864);
    f2bf<<<(147456 / 4 + 255) / 256, 256>>>(fc1_w,  wbf + 147456, 147456);
    f2bf<<<(147456 / 4 + 255) / 256, 256>>>(fc2_w,  wbf + 294912, 147456);

    gemm_bf16<0, 192, 576, 64><<<dim3(9, 1024), 256, SM64>>>(xbf, wbf, qkv_b, nullptr, nullptr, qkvh);
    attn_kernel<<<12288, 128>>>(rpb, att);
    gemm_bf16<1, 192, 192, 64><<<dim3(3, 1024), 256, SM64>>>(att, wbf + 110592, proj_b, x, x1, x1bf);
    gemm_bf16<2, 192, 768, 128><<<dim3(6, 1024), 256, SM128>>>(x1bf, wbf + 147456, fc1_b, nullptr, nullptr, h);
    gemm_bf16<3, 768, 192, 64><<<dim3(3, 1024), 256, SM64>>>(h, wbf + 294912, fc2_b, x1, out, nullptr);
}

// round 13
// speedup vs baseline: 2.2155x; 1.3560x over previous
#include <cuda_runtime.h>
#include <cuda_bf16.h>
#include <math.h>
#include <stdint.h>

#define NROWS 131072
#define QKV_STRIDE 25165824ll

__device__ __nv_bfloat16 g_qkvh[3ll * 25165824];  // q,k,v bf16
__device__ __nv_bfloat16 g_xbf[25165824];
__device__ __nv_bfloat16 g_att[25165824];
__device__ float g_x1[25165824];
__device__ __nv_bfloat16 g_x1bf[25165824];
__device__ __nv_bfloat16 g_h[100663296ll];
__device__ __nv_bfloat16 g_wbf[442368];

__device__ __forceinline__ int map_row(int r) {
    int wid = r >> 6, n = r & 63;
    int b = wid >> 6, w = wid & 63;
    int h  = ((w >> 3) << 3) + (n >> 3);
    int ww = ((w & 7) << 3) + (n & 7);
    int ho = (h + 4) & 63, wo = (ww + 4) & 63;
    return (b << 12) + (ho << 6) + wo;
}
__device__ __forceinline__ int region(int x) { return x < 56 ? 0 : (x < 60 ? 1 : 2); }

__device__ __forceinline__ void cpa16(unsigned s, const void* g) {
    asm volatile("cp.async.cg.shared.global [%0], [%1], 16;" :: "r"(s), "l"(g));
}
#define CP_COMMIT() asm volatile("cp.async.commit_group;")
#define CP_WAIT1()  asm volatile("cp.async.wait_group 1;")
#define CP_WAIT0()  asm volatile("cp.async.wait_group 0;" ::: "memory")

__device__ __forceinline__ void ldsm4(unsigned* r, unsigned a) {
    asm volatile("ldmatrix.sync.aligned.m8n8.x4.shared.b16 {%0,%1,%2,%3}, [%4];"
        : "=r"(r[0]), "=r"(r[1]), "=r"(r[2]), "=r"(r[3]) : "r"(a));
}
__device__ __forceinline__ void ldsm4t(unsigned* r, unsigned a) {
    asm volatile("ldmatrix.sync.aligned.m8n8.x4.trans.shared.b16 {%0,%1,%2,%3}, [%4];"
        : "=r"(r[0]), "=r"(r[1]), "=r"(r[2]), "=r"(r[3]) : "r"(a));
}
__device__ __forceinline__ void mma_bf16(float* d, const unsigned* a, const unsigned* b) {
    asm volatile(
        "mma.sync.aligned.m16n8k16.row.col.f32.bf16.bf16.f32 "
        "{%0,%1,%2,%3}, {%4,%5,%6,%7}, {%8,%9}, {%0,%1,%2,%3};"
        : "+f"(d[0]), "+f"(d[1]), "+f"(d[2]), "+f"(d[3])
        : "r"(a[0]), "r"(a[1]), "r"(a[2]), "r"(a[3]), "r"(b[0]), "r"(b[1]));
}
__device__ __forceinline__ void mma_bf16_2(float* d, const unsigned* a, unsigned b0, unsigned b1) {
    asm volatile(
        "mma.sync.aligned.m16n8k16.row.col.f32.bf16.bf16.f32 "
        "{%0,%1,%2,%3}, {%4,%5,%6,%7}, {%8,%9}, {%0,%1,%2,%3};"
        : "+f"(d[0]), "+f"(d[1]), "+f"(d[2]), "+f"(d[3])
        : "r"(a[0]), "r"(a[1]), "r"(a[2]), "r"(a[3]), "r"(b0), "r"(b1));
}
__device__ __forceinline__ unsigned pack2(float e, float o) {
    __nv_bfloat162 h = __floats2bfloat162_rn(e, o);
    return *reinterpret_cast<unsigned*>(&h);
}

template<int MODE, int NCOLS>
__device__ __forceinline__ void epi_store(
    int r, int c, float v, const float* __restrict__ bias,
    const float* __restrict__ aux, float* __restrict__ outf,
    __nv_bfloat16* __restrict__ outh)
{
    v += bias[c];
    if (MODE == 0) {
        int which = c / 192, rem = c % 192;
        int head = rem >> 5, hd = rem & 31;
        if (which == 0) v *= 0.17677669529663689f;
        int wid = r >> 6, n = r & 63;
        outh[(long)which * QKV_STRIDE + (((long)(wid * 6 + head) * 64 + n) * 32 + hd)] =
            __float2bfloat16(v);
    } else if (MODE == 1) {
        long o = (long)map_row(r) * 192 + c;
        float s = aux[o] + v;
        outf[o] = s;
        outh[o] = __float2bfloat16(s);
    } else if (MODE == 2) {
        outh[(long)r * NCOLS + c] =
            __float2bfloat16(0.5f * v * (1.0f + erff(v * 0.7071067811865476f)));
    } else {
        long o = (long)r * NCOLS + c;
        outf[o] = aux[o] + v;
    }
}

// ---------------------------------------------------------------------------
// bf16 mma.sync GEMM (unchanged from round 11).
// ---------------------------------------------------------------------------
#define A_STAGE 10240   // 128 rows * 80B

template<int MODE, int K, int NCOLS, int NTILE>
__global__ __launch_bounds__(256) void gemm_bf16(
    const __nv_bfloat16* __restrict__ A, const __nv_bfloat16* __restrict__ Bm,
    const float* __restrict__ bias, const float* __restrict__ aux,
    float* __restrict__ outf, __nv_bfloat16* __restrict__ outh)
{
    constexpr int BROW = 2 * NTILE + 16;
    constexpr int B_STAGE = 32 * BROW;
    constexpr int G  = NTILE / 32;
    constexpr int NI = NTILE / 16;
    constexpr int CPT = NTILE / 64;

    extern __shared__ char smem_raw[];
    const unsigned aBase = (unsigned)__cvta_generic_to_shared(smem_raw);
    const unsigned bBase = aBase + 3 * A_STAGE;

    const int mBase = blockIdx.y * 128;
    const int nBase = blockIdx.x * NTILE;
    const int t = threadIdx.x;
    const int lane = t & 31, warp = t >> 5;
    const int warpM = warp >> 1, warpN = warp & 1;
    const int lq = lane >> 2, lr = lane & 3;

    const int ar = t >> 2;
    const int ac = (t & 3) * 8;
    long row1 = (MODE == 0) ? (long)map_row(mBase + ar)      : (long)(mBase + ar);
    long row2 = (MODE == 0) ? (long)map_row(mBase + ar + 64) : (long)(mBase + ar + 64);
    const __nv_bfloat16* Ap1 = A + row1 * K + ac;
    const __nv_bfloat16* Ap2 = A + row2 * K + ac;
    const unsigned sA1 = aBase + ar * 80 + (t & 3) * 16;
    const unsigned sA2 = sA1 + 64 * 80;
    const int bk = t >> 3;
    const __nv_bfloat16* Bp = Bm + (long)bk * NCOLS + nBase + (t & 7) * 8;
    const unsigned sB = bBase + bk * BROW + (t & 7) * 16;

    float acc[2][NI][4];
    #pragma unroll
    for (int mi = 0; mi < 2; mi++)
        #pragma unroll
        for (int ni = 0; ni < NI; ni++)
            #pragma unroll
            for (int e = 0; e < 4; e++) acc[mi][ni][e] = 0.f;

    const int NK = K / 32;
    #pragma unroll
    for (int s = 0; s < 2; s++) {
        cpa16(sA1 + s * A_STAGE, Ap1 + s * 32);
        cpa16(sA2 + s * A_STAGE, Ap2 + s * 32);
        #pragma unroll
        for (int cc = 0; cc < CPT; cc++)
            cpa16(sB + s * B_STAGE + cc * 128, Bp + (long)s * 32 * NCOLS + cc * 64);
        CP_COMMIT();
    }

    for (int kt = 0; kt < NK; kt++) {
        const int s = kt % 3;
        CP_WAIT1();
        __syncthreads();
        if (kt + 2 < NK) {
            const int s2 = (kt + 2) % 3;
            cpa16(sA1 + s2 * A_STAGE, Ap1 + (kt + 2) * 32);
            cpa16(sA2 + s2 * A_STAGE, Ap2 + (kt + 2) * 32);
            #pragma unroll
            for (int cc = 0; cc < CPT; cc++)
                cpa16(sB + s2 * B_STAGE + cc * 128,
                      Bp + (long)(kt + 2) * 32 * NCOLS + cc * 64);
        }
        CP_COMMIT();

        const unsigned as0 = aBase + s * A_STAGE;
        const unsigned bs0 = bBase + s * B_STAGE;
        #pragma unroll
        for (int k16 = 0; k16 < 2; k16++) {
            unsigned af[2][4], bq[G][4];
            #pragma unroll
            for (int mi = 0; mi < 2; mi++)
                ldsm4(af[mi], as0 + (warpM * 32 + mi * 16 + (lane & 15)) * 80
                              + k16 * 32 + (lane >> 4) * 16);
            #pragma unroll
            for (int g = 0; g < G; g++)
                ldsm4t(bq[g], bs0 + (k16 * 16 + (lane & 15)) * BROW
                              + (warpN * (NTILE / 2) + g * 16 + ((lane >> 4) << 3)) * 2);
            #pragma unroll
            for (int mi = 0; mi < 2; mi++)
                #pragma unroll
                for (int ni = 0; ni < NI; ni++)
                    mma_bf16(acc[mi][ni], af[mi], &bq[ni >> 1][(ni & 1) * 2]);
        }
    }

    #pragma unroll
    for (int mi = 0; mi < 2; mi++) {
        int r0 = mBase + warpM * 32 + mi * 16 + lq;
        #pragma unroll
        for (int ni = 0; ni < NI; ni++) {
            int c0 = nBase + warpN * (NTILE / 2) + ni * 8 + lr * 2;
            epi_store<MODE, NCOLS>(r0,     c0,     acc[mi][ni][0], bias, aux, outf, outh);
            epi_store<MODE, NCOLS>(r0,     c0 + 1, acc[mi][ni][1], bias, aux, outf, outh);
            epi_store<MODE, NCOLS>(r0 + 8, c0,     acc[mi][ni][2], bias, aux, outf, outh);
            epi_store<MODE, NCOLS>(r0 + 8, c0 + 1, acc[mi][ni][3], bias, aux, outf, outh);
        }
    }
}

// ---------------------------------------------------------------------------
__global__ void f2bf(const float* __restrict__ in, __nv_bfloat16* __restrict__ out, int n) {
    int i = (blockIdx.x * blockDim.x + threadIdx.x) * 4;
    if (i >= n) return;
    float4 v = *(const float4*)(in + i);
    *(__nv_bfloat162*)(out + i)     = __floats2bfloat162_rn(v.x, v.y);
    *(__nv_bfloat162*)(out + i + 2) = __floats2bfloat162_rn(v.z, v.w);
}

// ---------------------------------------------------------------------------
// Tensor-core attention: one block per (window, head), 4 warps, 16 rows/warp.
// S = Q@K^T via mma (K [n][k] -> ldsm4 b-frags), softmax in C-frag registers,
// re-pack C frags as A frags for P@V (V [k][n] -> ldsm4t), 1/sum in epilogue.
// ---------------------------------------------------------------------------
__global__ __launch_bounds__(128) void attn_kernel(
    const float* __restrict__ rpb, __nv_bfloat16* __restrict__ out)
{
    __shared__ __align__(16) __nv_bfloat16 Qs[64 * 40];
    __shared__ __align__(16) __nv_bfloat16 Ks[64 * 40];
    __shared__ __align__(16) __nv_bfloat16 Vs[64 * 40];

    const int bh = blockIdx.x;
    const int wid = bh / 6, head = bh - wid * 6;
    const int w = wid & 63;
    const int t = threadIdx.x, lane = t & 31, warp = t >> 5;
    const int lq = lane >> 2, lr = lane & 3;

    const unsigned qA = (unsigned)__cvta_generic_to_shared(Qs);
    const unsigned kA = (unsigned)__cvta_generic_to_shared(Ks);
    const unsigned vA = (unsigned)__cvta_generic_to_shared(Vs);
    const __nv_bfloat16* qb = g_qkvh + (long)bh * 2048;
    const __nv_bfloat16* kb = qb + QKV_STRIDE;
    const __nv_bfloat16* vb = kb + QKV_STRIDE;

    #pragma unroll
    for (int c = t; c < 256; c += 128) {
        int row = c >> 2, o = c & 3;
        unsigned so = row * 80 + o * 16;
        const __nv_bfloat16* go = qb + row * 32 + o * 8;
        cpa16(qA + so, go);
        cpa16(kA + so, go + QKV_STRIDE);
        cpa16(vA + so, go + 2 * QKV_STRIDE);
    }
    CP_COMMIT();
    CP_WAIT0();
    __syncthreads();

    // ---- S = Q @ K^T  (m16 rows x n64 cols, k32) ----
    float sc[8][4];
    #pragma unroll
    for (int ni = 0; ni < 8; ni++)
        #pragma unroll
        for (int e = 0; e < 4; e++) sc[ni][e] = 0.f;

    unsigned af[2][4];
    #pragma unroll
    for (int kc = 0; kc < 2; kc++)
        ldsm4(af[kc], qA + (warp * 16 + (lane & 15)) * 80 + kc * 32 + (lane >> 4) * 16);
    #pragma unroll
    for (int kc = 0; kc < 2; kc++) {
        unsigned bq[4][4];
        #pragma unroll
        for (int g = 0; g < 4; g++)
            ldsm4(bq[g], kA + (g * 16 + (lane & 15)) * 80 + kc * 32 + (lane >> 4) * 16);
        #pragma unroll
        for (int ni = 0; ni < 8; ni++)
            mma_bf16_2(sc[ni], af[kc], bq[ni >> 1][ni & 1], bq[ni >> 1][2 + (ni & 1)]);
    }

    // ---- bias + mask + softmax (in registers) ----
    const int hb = (w >> 3) << 3, wbx = (w & 7) << 3;
    const int r0 = warp * 16 + lq, r1 = r0 + 8;
    const int rh0 = r0 >> 3, rw0 = r0 & 7, rh1 = r1 >> 3, rw1 = r1 & 7;
    const int reg0 = region(hb + rh0) * 3 + region(wbx + rw0);
    const int reg1 = region(hb + rh1) * 3 + region(wbx + rw1);
    const int base0 = ((rh0 + 7) * 15 + rw0 + 7) * 6 + head;
    const int base1 = ((rh1 + 7) * 15 + rw1 + 7) * 6 + head;

    float mx0 = -1e30f, mx1 = -1e30f;
    #pragma unroll
    for (int ni = 0; ni < 8; ni++) {
        #pragma unroll
        for (int e = 0; e < 2; e++) {
            int col = ni * 8 + 2 * lr + e;
            int ch = col >> 3, cw = col & 7;
            int cOff = (ch * 15 + cw) * 6;
            int regC = region(hb + ch) * 3 + region(wbx + cw);
            float v0 = sc[ni][e]     + __ldg(rpb + base0 - cOff) + (regC != reg0 ? -100.f : 0.f);
            float v1 = sc[ni][2 + e] + __ldg(rpb + base1 - cOff) + (regC != reg1 ? -100.f : 0.f);
            sc[ni][e] = v0; sc[ni][2 + e] = v1;
            mx0 = fmaxf(mx0, v0); mx1 = fmaxf(mx1, v1);
        }
    }
    mx0 = fmaxf(mx0, __shfl_xor_sync(0xffffffffu, mx0, 1));
    mx0 = fmaxf(mx0, __shfl_xor_sync(0xffffffffu, mx0, 2));
    mx1 = fmaxf(mx1, __shfl_xor_sync(0xffffffffu, mx1, 1));
    mx1 = fmaxf(mx1, __shfl_xor_sync(0xffffffffu, mx1, 2));

    float s0 = 0.f, s1 = 0.f;
    #pragma unroll
    for (int ni = 0; ni < 8; ni++) {
        #pragma unroll
        for (int e = 0; e < 2; e++) {
            float e0 = __expf(sc[ni][e] - mx0);
            float e1 = __expf(sc[ni][2 + e] - mx1);
            sc[ni][e] = e0; sc[ni][2 + e] = e1;
            s0 += e0; s1 += e1;
        }
    }
    s0 += __shfl_xor_sync(0xffffffffu, s0, 1);
    s0 += __shfl_xor_sync(0xffffffffu, s0, 2);
    s1 += __shfl_xor_sync(0xffffffffu, s1, 1);
    s1 += __shfl_xor_sync(0xffffffffu, s1, 2);
    const float inv0 = 1.f / s0, inv1 = 1.f / s1;

    // ---- re-pack P into A frags; O = P @ V (m16 x n32, k64) ----
    unsigned pa[4][4];
    #pragma unroll
    for (int kc2 = 0; kc2 < 4; kc2++) {
        pa[kc2][0] = pack2(sc[2 * kc2][0],     sc[2 * kc2][1]);
        pa[kc2][1] = pack2(sc[2 * kc2][2],     sc[2 * kc2][3]);
        pa[kc2][2] = pack2(sc[2 * kc2 + 1][0], sc[2 * kc2 + 1][1]);
        pa[kc2][3] = pack2(sc[2 * kc2 + 1][2], sc[2 * kc2 + 1][3]);
    }
    float o4[4][4];
    #pragma unroll
    for (int nf = 0; nf < 4; nf++)
        #pragma unroll
        for (int e = 0; e < 4; e++) o4[nf][e] = 0.f;
    #pragma unroll
    for (int kc2 = 0; kc2 < 4; kc2++) {
        unsigned bv[2][4];
        #pragma unroll
        for (int g2 = 0; g2 < 2; g2++)
            ldsm4t(bv[g2], vA + (kc2 * 16 + (lane & 15)) * 80
                           + (g2 * 16 + ((lane >> 4) << 3)) * 2);
        #pragma unroll
        for (int nf = 0; nf < 4; nf++)
            mma_bf16(o4[nf], pa[kc2], &bv[nf >> 1][2 * (nf & 1)]);
    }

    const long grow = (long)(wid * 64 + r0);
    #pragma unroll
    for (int nf = 0; nf < 4; nf++) {
        int col = head * 32 + nf * 8 + 2 * lr;
        *(__nv_bfloat162*)(out + grow * 192 + col) =
            __floats2bfloat162_rn(o4[nf][0] * inv0, o4[nf][1] * inv0);
        *(__nv_bfloat162*)(out + (grow + 8) * 192 + col) =
            __floats2bfloat162_rn(o4[nf][2] * inv1, o4[nf][3] * inv1);
    }
}

// ---------------------------------------------------------------------------
extern "C" void kernel_launch(void* const* d_in, const int* in_sizes, int n_in,
                              void* d_out, int out_size)
{
    const float* x      = (const float*)d_in[0];
    const float* rpb    = (const float*)d_in[1];
    const float* qkv_w  = (const float*)d_in[2];
    const float* qkv_b  = (const float*)d_in[3];
    const float* proj_w = (const float*)d_in[4];
    const float* proj_b = (const float*)d_in[5];
    const float* fc1_w  = (const float*)d_in[6];
    const float* fc1_b  = (const float*)d_in[7];
    const float* fc2_w  = (const float*)d_in[8];
    const float* fc2_b  = (const float*)d_in[9];
    float* out = (float*)d_out;

    float *x1;
    __nv_bfloat16 *qkvh, *xbf, *att, *x1bf, *h, *wbf;
    cudaGetSymbolAddress((void**)&qkvh, g_qkvh);
    cudaGetSymbolAddress((void**)&xbf,  g_xbf);
    cudaGetSymbolAddress((void**)&att,  g_att);
    cudaGetSymbolAddress((void**)&x1,   g_x1);
    cudaGetSymbolAddress((void**)&x1bf, g_x1bf);
    cudaGetSymbolAddress((void**)&h,    g_h);
    cudaGetSymbolAddress((void**)&wbf,  g_wbf);

    constexpr int SM64  = 3 * (A_STAGE + 32 * 144);
    constexpr int SM128 = 3 * (A_STAGE + 32 * 272);
    cudaFuncSetAttribute(gemm_bf16<0, 192, 576, 64>,  cudaFuncAttributeMaxDynamicSharedMemorySize, SM64);
    cudaFuncSetAttribute(gemm_bf16<1, 192, 192, 64>,  cudaFuncAttributeMaxDynamicSharedMemorySize, SM64);
    cudaFuncSetAttribute(gemm_bf16<2, 192, 768, 128>, cudaFuncAttributeMaxDynamicSharedMemorySize, SM128);
    cudaFuncSetAttribute(gemm_bf16<3, 768, 192, 64>,  cudaFuncAttributeMaxDynamicSharedMemorySize, SM64);

    f2bf<<<25165824 / 4 / 256, 256>>>(x, xbf, 25165824);
    f2bf<<<(110592 / 4 + 255) / 256, 256>>>(qkv_w,  wbf,          110592);
    f2bf<<<(36864  / 4 + 255) / 256, 256>>>(proj_w, wbf + 110592, 36864);
    f2bf<<<(147456 / 4 + 255) / 256, 256>>>(fc1_w,  wbf + 147456, 147456);
    f2bf<<<(147456 / 4 + 255) / 256, 256>>>(fc2_w,  wbf + 294912, 147456);

    gemm_bf16<0, 192, 576, 64><<<dim3(9, 1024), 256, SM64>>>(xbf, wbf, qkv_b, nullptr, nullptr, qkvh);
    attn_kernel<<<12288, 128>>>(rpb, att);
    gemm_bf16<1, 192, 192, 64><<<dim3(3, 1024), 256, SM64>>>(att, wbf + 110592, proj_b, x, x1, x1bf);
    gemm_bf16<2, 192, 768, 128><<<dim3(6, 1024), 256, SM128>>>(x1bf, wbf + 147456, fc1_b, nullptr, nullptr, h);
    gemm_bf16<3, 768, 192, 64><<<dim3(3, 1024), 256, SM64>>>(h, wbf + 294912, fc2_b, x1, out, nullptr);
}